// round 4
// baseline (speedup 1.0000x reference)
#include <cuda_runtime.h>
#include <cuda_bf16.h>

// Problem constants
#define T_STEPS 4096
#define M_BATCH 512
#define D_IN    11
#define NH      51
#define G4      204          // 4*NH gate columns
#define A1S     64           // act1 row stride: x[11] | h1[51] | 2 pad
#define A2S     104          // act2 row stride: h1[51] | h2[51] | 2 pad
#define ROWS    4            // batch rows per block
#define THREADS 512          // 16 warps; 2-way K-split over 204 gate columns
#define BLOCKS  128          // 128*4 = 512 rows

__device__ __forceinline__ float sigf(float x) {
    return __fdividef(1.0f, 1.0f + __expf(-x));
}
__device__ __forceinline__ float tanh_f(float x) {
    return __fdividef(2.0f, 1.0f + __expf(-2.0f * x)) - 1.0f;
}

// packed 2xfp32 FMA (Blackwell f32x2 pipe): d = a*b + c per 32-bit lane
__device__ __forceinline__ unsigned long long fma2(unsigned long long a,
                                                   unsigned long long b,
                                                   unsigned long long c) {
    unsigned long long d;
    asm("fma.rn.f32x2 %0, %1, %2, %3;" : "=l"(d) : "l"(a), "l"(b), "l"(c));
    return d;
}
__device__ __forceinline__ unsigned long long pack2(float lo, float hi) {
    unsigned long long r;
    asm("mov.b64 %0, {%1, %2};" : "=l"(r) : "f"(lo), "f"(hi));
    return r;
}
__device__ __forceinline__ float sum2(unsigned long long v) {
    float lo, hi;
    asm("mov.b64 {%0, %1}, %2;" : "=f"(lo), "=f"(hi) : "l"(v));
    return lo + hi;
}

__global__ void __launch_bounds__(THREADS, 1)
lstm2_persistent_kernel(const float* __restrict__ x,
                        const float* __restrict__ Wih1, const float* __restrict__ Whh1,
                        const float* __restrict__ bih1, const float* __restrict__ bhh1,
                        const float* __restrict__ Wih2, const float* __restrict__ Whh2,
                        const float* __restrict__ bih2, const float* __restrict__ bhh2,
                        const float* __restrict__ Wlin, const float* __restrict__ blin,
                        float* __restrict__ out)
{
    __shared__ float A1[ROWS][A1S];      // activations layer1 input
    __shared__ float A2[ROWS][A2S];      // h1 | h2
    __shared__ float GSa[ROWS][G4];      // K-half-0 gate partials
    __shared__ float GSb[ROWS][G4];      // K-half-1 gate partials
    __shared__ float PO[ROWS][64];       // output partials

    const int tid   = threadIdx.x;
    const int mbase = blockIdx.x * ROWS;
    const int hf    = tid >> 8;          // K-half (0/1)
    const int cidx  = tid & 255;         // gate column candidate
    const bool gate_active = (cidx < G4);

    // ---- per-thread REGISTER weights (packed f32x2 k-pairs), loaded once ----
    unsigned long long wL1[16];          // 32 floats: half of layer1 K (64 padded)
    unsigned long long wL2[26];          // 52 floats: half of layer2 K (104 padded)
    #pragma unroll
    for (int i = 0; i < 16; ++i) wL1[i] = 0ull;
    #pragma unroll
    for (int i = 0; i < 26; ++i) wL2[i] = 0ull;

    if (gate_active) {
        #pragma unroll
        for (int i = 0; i < 16; ++i) {
            int k0 = hf * 32 + 2 * i;
            float lo = 0.0f, hi = 0.0f;
            if (k0 < D_IN)            lo = Wih1[cidx * D_IN + k0];
            else if (k0 < D_IN + NH)  lo = Whh1[cidx * NH + (k0 - D_IN)];
            int k1 = k0 + 1;
            if (k1 < D_IN)            hi = Wih1[cidx * D_IN + k1];
            else if (k1 < D_IN + NH)  hi = Whh1[cidx * NH + (k1 - D_IN)];
            wL1[i] = pack2(lo, hi);
        }
        #pragma unroll
        for (int i = 0; i < 26; ++i) {
            int k0 = hf * 52 + 2 * i;
            float lo = 0.0f, hi = 0.0f;
            if (k0 < NH)              lo = Wih2[cidx * NH + k0];
            else if (k0 < 2 * NH)     lo = Whh2[cidx * NH + (k0 - NH)];
            int k1 = k0 + 1;
            if (k1 < NH)              hi = Wih2[cidx * NH + k1];
            else if (k1 < 2 * NH)     hi = Whh2[cidx * NH + (k1 - NH)];
            wL2[i] = pack2(lo, hi);
        }
    }

    // ---- zero activation / scratch buffers ----
    for (int i = tid; i < ROWS * A1S; i += THREADS) (&A1[0][0])[i] = 0.0f;
    for (int i = tid; i < ROWS * A2S; i += THREADS) (&A2[0][0])[i] = 0.0f;
    for (int i = tid; i < ROWS * 64;  i += THREADS) (&PO[0][0])[i] = 0.0f;

    if (tid < ROWS * D_IN) {
        int r = tid / D_IN, k = tid - r * D_IN;
        A1[r][k] = x[(0 * M_BATCH + mbase + r) * D_IN + k];
    }

    // per-thread constants / state (bias only added by K-half-0 thread)
    float bias1 = 0.0f, bias2 = 0.0f, wl = 0.0f;
    float c1 = 0.0f, c2 = 0.0f;
    int erow = 0, en = 0;
    if (tid < G4) {                      // half-0 gate threads double as epilogue threads
        bias1 = bih1[tid] + bhh1[tid];
        bias2 = bih2[tid] + bhh2[tid];
        erow = tid / NH;
        en   = tid - erow * NH;
        wl   = Wlin[en];
    }
    const float bl = blin[0];
    float* GH = hf ? &GSb[0][0] : &GSa[0][0];

    __syncthreads();

    for (int t = 0; t < T_STEPS; ++t) {
        // prefetch x_{t+1} (hidden under S0)
        float xr = 0.0f;
        int pr = 0, pk = 0;
        if (tid < ROWS * D_IN) {
            pr = tid / D_IN;
            pk = tid - pr * D_IN;
            if (t + 1 < T_STEPS)
                xr = x[((t + 1) * M_BATCH + mbase + pr) * D_IN + pk];
        }

        // ---- S0: layer-1 gates: register weights x broadcast activations ----
        if (gate_active) {
            unsigned long long acc[ROWS];
            #pragma unroll
            for (int r = 0; r < ROWS; ++r) acc[r] = pack2(bias1, 0.0f);
            const int q0 = hf * 8;                       // ul2 indices [0,8) / [8,16)
            #pragma unroll
            for (int q = 0; q < 8; ++q) {
                #pragma unroll
                for (int r = 0; r < ROWS; ++r) {
                    ulonglong2 a = reinterpret_cast<const ulonglong2*>(&A1[r][0])[q0 + q];
                    acc[r] = fma2(wL1[2 * q],     a.x, acc[r]);
                    acc[r] = fma2(wL1[2 * q + 1], a.y, acc[r]);
                }
            }
            #pragma unroll
            for (int r = 0; r < ROWS; ++r) GH[r * G4 + cidx] = sum2(acc[r]);
        }
        __syncthreads();

        // ---- S1: layer-1 epilogue (thread = (row, n)) ----
        if (tid < G4) {
            float gi = GSa[erow][en]          + GSb[erow][en];
            float gf = GSa[erow][NH + en]     + GSb[erow][NH + en];
            float gg = GSa[erow][2 * NH + en] + GSb[erow][2 * NH + en];
            float go = GSa[erow][3 * NH + en] + GSb[erow][3 * NH + en];
            c1 = sigf(gf) * c1 + sigf(gi) * tanh_f(gg);
            float h = sigf(go) * tanh_f(c1);
            A2[erow][en] = h;                 // layer-2 input (this step)
            A1[erow][D_IN + en] = h;          // layer-1 h input (next step)
        }
        if (tid < ROWS * D_IN) A1[pr][pk] = xr;   // x_{t+1}
        __syncthreads();

        // ---- S2: layer-2 gates ----
        if (gate_active) {
            unsigned long long acc[ROWS];
            #pragma unroll
            for (int r = 0; r < ROWS; ++r) acc[r] = pack2(bias2, 0.0f);
            const int q0 = hf * 13;                      // ul2 indices [0,13) / [13,26)
            #pragma unroll
            for (int q = 0; q < 13; ++q) {
                #pragma unroll
                for (int r = 0; r < ROWS; ++r) {
                    ulonglong2 a = reinterpret_cast<const ulonglong2*>(&A2[r][0])[q0 + q];
                    acc[r] = fma2(wL2[2 * q],     a.x, acc[r]);
                    acc[r] = fma2(wL2[2 * q + 1], a.y, acc[r]);
                }
            }
            #pragma unroll
            for (int r = 0; r < ROWS; ++r) GH[r * G4 + cidx] = sum2(acc[r]);
        }
        __syncthreads();

        // ---- S3: layer-2 epilogue ----
        if (tid < G4) {
            float gi = GSa[erow][en]          + GSb[erow][en];
            float gf = GSa[erow][NH + en]     + GSb[erow][NH + en];
            float gg = GSa[erow][2 * NH + en] + GSb[erow][2 * NH + en];
            float go = GSa[erow][3 * NH + en] + GSb[erow][3 * NH + en];
            c2 = sigf(gf) * c2 + sigf(gi) * tanh_f(gg);
            float h = sigf(go) * tanh_f(c2);
            A2[erow][NH + en] = h;            // h2 for next step
            PO[erow][en] = h * wl;            // output partial
        }
        __syncthreads();

        // ---- S4: output reduction, warp r handles row r ----
        if (tid < 128) {
            int r = tid >> 5, lane = tid & 31;
            float v = PO[r][lane] + PO[r][32 + lane];   // [51..63] are zero
            #pragma unroll
            for (int off = 16; off > 0; off >>= 1)
                v += __shfl_down_sync(0xffffffffu, v, off);
            if (lane == 0)
                out[(mbase + r) * T_STEPS + t] = v + bl;
        }
        // next-iter S0 writes GSa/GSb only after S3's sync; PO rewritten only in next S3
    }
}

extern "C" void kernel_launch(void* const* d_in, const int* in_sizes, int n_in,
                              void* d_out, int out_size) {
    const float* x    = (const float*)d_in[0];
    const float* Wih1 = (const float*)d_in[1];
    const float* Whh1 = (const float*)d_in[2];
    const float* bih1 = (const float*)d_in[3];
    const float* bhh1 = (const float*)d_in[4];
    const float* Wih2 = (const float*)d_in[5];
    const float* Whh2 = (const float*)d_in[6];
    const float* bih2 = (const float*)d_in[7];
    const float* bhh2 = (const float*)d_in[8];
    const float* Wlin = (const float*)d_in[9];
    const float* blin = (const float*)d_in[10];
    float* out = (float*)d_out;

    lstm2_persistent_kernel<<<BLOCKS, THREADS>>>(
        x, Wih1, Whh1, bih1, bhh1, Wih2, Whh2, bih2, bhh2, Wlin, blin, out);
}

// round 6
// speedup vs baseline: 1.5787x; 1.5787x over previous
#include <cuda_runtime.h>
#include <cuda_bf16.h>

// Problem constants
#define T_STEPS 4096
#define M_BATCH 512
#define D_IN    11
#define NH      51
#define G4      204          // 4*NH gate columns
#define PW2     108          // padded K layer2 (h1[51]|h2[51] -> 108; 27*16B odd stride, conflict-free)
#define A1S     64           // act1 row stride: x[11] | h1[51] | 2 pad
#define A2S     104          // act2 row stride: h1[51] | h2[51] | 2 pad
#define ROWS    4            // batch rows per block
#define THREADS 416          // 13 warps; 2-way K-split over 204 gate columns (2*208)
#define BLOCKS  128          // 128*4 = 512 rows

// dynamic shared-memory float offsets
#define OW2   0
#define OA1   (G4*PW2)                    // 22032
#define OA2   (OA1 + ROWS*A1S)            // 22288
#define OGA   (OA2 + ROWS*A2S)            // 22704
#define OGB   (OGA + ROWS*G4)             // 23520
#define OPO   (OGB + ROWS*G4)             // 24336
#define SMEMF (OPO + ROWS*64)             // 24592 floats
#define SMEMB (SMEMF * 4)                 // 98368 bytes

// fast tanh (MUFU.TANH, sm_75+)
__device__ __forceinline__ float tanha(float x) {
    float y;
    asm("tanh.approx.f32 %0, %1;" : "=f"(y) : "f"(x));
    return y;
}
__device__ __forceinline__ float siga(float x) {
    return fmaf(0.5f, tanha(0.5f * x), 0.5f);
}

// packed 2xfp32 FMA (Blackwell f32x2 pipe)
__device__ __forceinline__ unsigned long long fma2(unsigned long long a,
                                                   unsigned long long b,
                                                   unsigned long long c) {
    unsigned long long d;
    asm("fma.rn.f32x2 %0, %1, %2, %3;" : "=l"(d) : "l"(a), "l"(b), "l"(c));
    return d;
}
__device__ __forceinline__ unsigned long long pack2(float lo, float hi) {
    unsigned long long r;
    asm("mov.b64 %0, {%1, %2};" : "=l"(r) : "f"(lo), "f"(hi));
    return r;
}
__device__ __forceinline__ float sum2(unsigned long long v) {
    float lo, hi;
    asm("mov.b64 {%0, %1}, %2;" : "=f"(lo), "=f"(hi) : "l"(v));
    return lo + hi;
}

__global__ void __launch_bounds__(THREADS, 1)
lstm2_persistent_kernel(const float* __restrict__ x,
                        const float* __restrict__ Wih1, const float* __restrict__ Whh1,
                        const float* __restrict__ bih1, const float* __restrict__ bhh1,
                        const float* __restrict__ Wih2, const float* __restrict__ Whh2,
                        const float* __restrict__ bih2, const float* __restrict__ bhh2,
                        const float* __restrict__ Wlin, const float* __restrict__ blin,
                        float* __restrict__ out)
{
    extern __shared__ float sm[];
    float* sW2 = sm + OW2;   // [204][108] layer2 weights (h1|h2, padded)
    float* A1  = sm + OA1;   // [4][64]
    float* A2  = sm + OA2;   // [4][104]
    float* GSa = sm + OGA;   // [4][204] K-half-0 partials
    float* GSb = sm + OGB;   // [4][204] K-half-1 partials
    float* PO  = sm + OPO;   // [4][64]

    const int tid   = threadIdx.x;
    const int mbase = blockIdx.x * ROWS;
    const int hf    = (tid >= 208) ? 1 : 0;   // K-half
    const int cidx  = tid - 208 * hf;         // gate column candidate (0..207)
    const bool gate_active = (cidx < G4);

    // ---- layer-1 weights: per-thread REGISTERS (16 u64 = 32 floats, half K) ----
    unsigned long long wL1[16];
    #pragma unroll
    for (int i = 0; i < 16; ++i) wL1[i] = 0ull;
    if (gate_active) {
        #pragma unroll
        for (int i = 0; i < 16; ++i) {
            int k0 = hf * 32 + 2 * i;
            float lo = 0.0f, hi = 0.0f;
            if (k0 < D_IN)            lo = Wih1[cidx * D_IN + k0];
            else if (k0 < D_IN + NH)  lo = Whh1[cidx * NH + (k0 - D_IN)];
            int k1 = k0 + 1;
            if (k1 < D_IN)            hi = Wih1[cidx * D_IN + k1];
            else if (k1 < D_IN + NH)  hi = Whh1[cidx * NH + (k1 - D_IN)];
            wL1[i] = pack2(lo, hi);
        }
    }

    // ---- layer-2 weights into shared (transposed, padded) ----
    for (int i = tid; i < G4 * PW2; i += THREADS) {
        int c = i / PW2, k = i - c * PW2;
        float v = 0.0f;
        if (k < NH)            v = Wih2[c * NH + k];
        else if (k < 2 * NH)   v = Whh2[c * NH + (k - NH)];
        sW2[i] = v;
    }
    for (int i = tid; i < ROWS * A1S; i += THREADS) A1[i] = 0.0f;
    for (int i = tid; i < ROWS * A2S; i += THREADS) A2[i] = 0.0f;
    for (int i = tid; i < ROWS * 64;  i += THREADS) PO[i] = 0.0f;

    if (tid < ROWS * D_IN) {
        int r = tid / D_IN, k = tid - r * D_IN;
        A1[r * A1S + k] = x[(0 * M_BATCH + mbase + r) * D_IN + k];
    }

    // per-thread constants / state (bias only added by K-half-0 thread)
    float bias1 = 0.0f, bias2 = 0.0f, wl = 0.0f;
    float c1 = 0.0f, c2 = 0.0f;
    int erow = 0, en = 0;
    if (tid < G4) {                      // half-0 gate threads double as epilogue threads
        bias1 = bih1[tid] + bhh1[tid];
        bias2 = bih2[tid] + bhh2[tid];
        erow = tid / NH;
        en   = tid - erow * NH;
        wl   = Wlin[en];
    }
    const float bl = blin[0];
    float* GH = hf ? GSb : GSa;

    __syncthreads();

    for (int t = 0; t < T_STEPS; ++t) {
        // prefetch x_{t+1} (hidden under S0)
        float xr = 0.0f;
        int pr = 0, pk = 0;
        if (tid < ROWS * D_IN) {
            pr = tid / D_IN;
            pk = tid - pr * D_IN;
            if (t + 1 < T_STEPS)
                xr = x[((t + 1) * M_BATCH + mbase + pr) * D_IN + pk];
        }

        // ---- S0: layer-1 gates: REGISTER weights x broadcast activations ----
        if (gate_active) {
            unsigned long long acc[ROWS];
            #pragma unroll
            for (int r = 0; r < ROWS; ++r) acc[r] = pack2(bias1, 0.0f);
            const int q0 = hf * 8;                     // ul2 indices [0,8)/[8,16)
            #pragma unroll
            for (int q = 0; q < 8; ++q) {
                #pragma unroll
                for (int r = 0; r < ROWS; ++r) {
                    ulonglong2 a = reinterpret_cast<const ulonglong2*>(A1 + r * A1S)[q0 + q];
                    acc[r] = fma2(wL1[2 * q],     a.x, acc[r]);
                    acc[r] = fma2(wL1[2 * q + 1], a.y, acc[r]);
                }
            }
            #pragma unroll
            for (int r = 0; r < ROWS; ++r) GH[r * G4 + cidx] = sum2(acc[r]);
        }
        __syncthreads();

        // ---- S1: layer-1 epilogue (thread = (row, n)) ----
        if (tid < G4) {
            float gi = GSa[erow * G4 + en]          + GSb[erow * G4 + en];
            float gf = GSa[erow * G4 + NH + en]     + GSb[erow * G4 + NH + en];
            float gg = GSa[erow * G4 + 2 * NH + en] + GSb[erow * G4 + 2 * NH + en];
            float go = GSa[erow * G4 + 3 * NH + en] + GSb[erow * G4 + 3 * NH + en];
            c1 = siga(gf) * c1 + siga(gi) * tanha(gg);
            float h = siga(go) * tanha(c1);
            A2[erow * A2S + en] = h;              // layer-2 input (this step)
            A1[erow * A1S + D_IN + en] = h;       // layer-1 h input (next step)
        }
        if (tid < ROWS * D_IN) A1[pr * A1S + pk] = xr;   // x_{t+1}
        __syncthreads();

        // ---- S2: layer-2 gates: smem weights ----
        if (gate_active) {
            unsigned long long acc[ROWS];
            #pragma unroll
            for (int r = 0; r < ROWS; ++r) acc[r] = pack2(bias2, 0.0f);
            const int q0 = hf * 13;                    // ul2 indices [0,13)/[13,26)
            const ulonglong2* wq = reinterpret_cast<const ulonglong2*>(sW2 + cidx * PW2);
            #pragma unroll
            for (int q = 0; q < 13; ++q) {
                ulonglong2 w = wq[q0 + q];
                #pragma unroll
                for (int r = 0; r < ROWS; ++r) {
                    ulonglong2 a = reinterpret_cast<const ulonglong2*>(A2 + r * A2S)[q0 + q];
                    acc[r] = fma2(w.x, a.x, acc[r]);
                    acc[r] = fma2(w.y, a.y, acc[r]);
                }
            }
            #pragma unroll
            for (int r = 0; r < ROWS; ++r) GH[r * G4 + cidx] = sum2(acc[r]);
        }
        __syncthreads();

        // ---- S3: layer-2 epilogue ----
        if (tid < G4) {
            float gi = GSa[erow * G4 + en]          + GSb[erow * G4 + en];
            float gf = GSa[erow * G4 + NH + en]     + GSb[erow * G4 + NH + en];
            float gg = GSa[erow * G4 + 2 * NH + en] + GSb[erow * G4 + 2 * NH + en];
            float go = GSa[erow * G4 + 3 * NH + en] + GSb[erow * G4 + 3 * NH + en];
            c2 = siga(gf) * c2 + siga(gi) * tanha(gg);
            float h = siga(go) * tanha(c2);
            A2[erow * A2S + NH + en] = h;         // h2 for next step
            PO[erow * 64 + en] = h * wl;          // output partial
        }
        __syncthreads();

        // ---- S4: output reduction, warp r handles row r ----
        if (tid < 128) {
            int r = tid >> 5, lane = tid & 31;
            float v = PO[r * 64 + lane] + PO[r * 64 + 32 + lane];  // [51..63] zero
            #pragma unroll
            for (int off = 16; off > 0; off >>= 1)
                v += __shfl_down_sync(0xffffffffu, v, off);
            if (lane == 0)
                out[(mbase + r) * T_STEPS + t] = v + bl;
        }
        // next-iter S0 writes GSa/GSb only after S3's sync; PO rewritten only in next S3
    }
}

extern "C" void kernel_launch(void* const* d_in, const int* in_sizes, int n_in,
                              void* d_out, int out_size) {
    const float* x    = (const float*)d_in[0];
    const float* Wih1 = (const float*)d_in[1];
    const float* Whh1 = (const float*)d_in[2];
    const float* bih1 = (const float*)d_in[3];
    const float* bhh1 = (const float*)d_in[4];
    const float* Wih2 = (const float*)d_in[5];
    const float* Whh2 = (const float*)d_in[6];
    const float* bih2 = (const float*)d_in[7];
    const float* bhh2 = (const float*)d_in[8];
    const float* Wlin = (const float*)d_in[9];
    const float* blin = (const float*)d_in[10];
    float* out = (float*)d_out;

    cudaFuncSetAttribute(lstm2_persistent_kernel,
                         cudaFuncAttributeMaxDynamicSharedMemorySize, SMEMB);
    lstm2_persistent_kernel<<<BLOCKS, THREADS, SMEMB>>>(
        x, Wih1, Whh1, bih1, bhh1, Wih2, Whh2, bih2, bhh2, Wlin, blin, out);
}

// round 9
// speedup vs baseline: 2.1526x; 1.3636x over previous
#include <cuda_runtime.h>
#include <cuda_bf16.h>

// Problem constants
#define T_STEPS 4096
#define M_BATCH 512
#define D_IN    11
#define NH      51
#define G4      204          // 4*NH gate columns
#define A1S     64           // act1 row stride: x[11] | h1[51] | 2 pad
#define A2S     104          // act2 row stride: h1[51] | h2[51] | 2 pad
#define ROWS    4            // batch rows per block
#define THREADS 256          // 8 warps; hf = tid>>7; 102 active col-pair threads per K-half
#define BLOCKS  128          // 128*4 = 512 rows
#define CP      102          // column-pairs (204/2)

// fast tanh (MUFU.TANH)
__device__ __forceinline__ float tanha(float x) {
    float y;
    asm("tanh.approx.f32 %0, %1;" : "=f"(y) : "f"(x));
    return y;
}
__device__ __forceinline__ float siga(float x) {
    return fmaf(0.5f, tanha(0.5f * x), 0.5f);
}

// packed 2xfp32 FMA (Blackwell f32x2 pipe)
__device__ __forceinline__ unsigned long long fma2(unsigned long long a,
                                                   unsigned long long b,
                                                   unsigned long long c) {
    unsigned long long d;
    asm("fma.rn.f32x2 %0, %1, %2, %3;" : "=l"(d) : "l"(a), "l"(b), "l"(c));
    return d;
}
__device__ __forceinline__ unsigned long long pack2(float lo, float hi) {
    unsigned long long r;
    asm("mov.b64 %0, {%1, %2};" : "=l"(r) : "f"(lo), "f"(hi));
    return r;
}
__device__ __forceinline__ float sum2(unsigned long long v) {
    float lo, hi;
    asm("mov.b64 {%0, %1}, %2;" : "=f"(lo), "=f"(hi) : "l"(v));
    return lo + hi;
}

__global__ void __launch_bounds__(THREADS, 1)
lstm2_persistent_kernel(const float* __restrict__ x,
                        const float* __restrict__ Wih1, const float* __restrict__ Whh1,
                        const float* __restrict__ bih1, const float* __restrict__ bhh1,
                        const float* __restrict__ Wih2, const float* __restrict__ Whh2,
                        const float* __restrict__ bih2, const float* __restrict__ bhh2,
                        const float* __restrict__ Wlin, const float* __restrict__ blin,
                        float* __restrict__ out)
{
    __shared__ float A1[ROWS][A1S];      // x[11] | h1[51] | pad
    __shared__ float A2[ROWS][A2S];      // h1[51] | h2[51] | pad
    __shared__ float GSa[ROWS][G4];      // K-half-0 partials
    __shared__ float GSb[ROWS][G4];      // K-half-1 partials
    __shared__ float PO[ROWS][64];       // output partials

    const int tid   = threadIdx.x;
    const int mbase = blockIdx.x * ROWS;
    const int hf    = tid >> 7;          // K-half, warp-uniform
    const int cp    = tid & 127;         // column-pair index
    const bool gate_active = (cp < CP);
    const int c0 = 2 * cp;               // first owned gate column

    // ---- ALL weights in per-thread registers (packed f32x2 k-pairs) ----
    // layer1: 2 cols x 16 u64 (half of padded K=64); layer2: 2 cols x 26 u64 (half of padded K=104)
    unsigned long long wL1[2][16];
    unsigned long long wL2[2][26];
    #pragma unroll
    for (int c = 0; c < 2; ++c) {
        #pragma unroll
        for (int i = 0; i < 16; ++i) wL1[c][i] = 0ull;
        #pragma unroll
        for (int i = 0; i < 26; ++i) wL2[c][i] = 0ull;
    }
    if (gate_active) {
        #pragma unroll
        for (int c = 0; c < 2; ++c) {
            const int col = c0 + c;
            #pragma unroll
            for (int i = 0; i < 16; ++i) {
                int k0 = hf * 32 + 2 * i;
                float lo = 0.0f, hi = 0.0f;
                if (k0 < D_IN)            lo = Wih1[col * D_IN + k0];
                else if (k0 < D_IN + NH)  lo = Whh1[col * NH + (k0 - D_IN)];
                int k1 = k0 + 1;
                if (k1 < D_IN)            hi = Wih1[col * D_IN + k1];
                else if (k1 < D_IN + NH)  hi = Whh1[col * NH + (k1 - D_IN)];
                wL1[c][i] = pack2(lo, hi);
            }
            #pragma unroll
            for (int i = 0; i < 26; ++i) {
                int k0 = hf * 52 + 2 * i;
                float lo = 0.0f, hi = 0.0f;
                if (k0 < NH)            lo = Wih2[col * NH + k0];
                else if (k0 < 2 * NH)   lo = Whh2[col * NH + (k0 - NH)];
                int k1 = k0 + 1;
                if (k1 < NH)            hi = Wih2[col * NH + k1];
                else if (k1 < 2 * NH)   hi = Whh2[col * NH + (k1 - NH)];
                wL2[c][i] = pack2(lo, hi);
            }
        }
    }

    // per-thread gate biases (added only by K-half-0 threads)
    float b1lo = 0.0f, b1hi = 0.0f, b2lo = 0.0f, b2hi = 0.0f;
    if (gate_active && hf == 0) {
        b1lo = bih1[c0] + bhh1[c0];
        b1hi = bih1[c0 + 1] + bhh1[c0 + 1];
        b2lo = bih2[c0] + bhh2[c0];
        b2hi = bih2[c0 + 1] + bhh2[c0 + 1];
    }

    // ---- zero buffers, load x_0 ----
    for (int i = tid; i < ROWS * A1S; i += THREADS) (&A1[0][0])[i] = 0.0f;
    for (int i = tid; i < ROWS * A2S; i += THREADS) (&A2[0][0])[i] = 0.0f;
    for (int i = tid; i < ROWS * 64;  i += THREADS) (&PO[0][0])[i] = 0.0f;
    if (tid < ROWS * D_IN) {
        int r = tid / D_IN, k = tid - r * D_IN;
        A1[r][k] = x[(0 * M_BATCH + mbase + r) * D_IN + k];
    }

    // epilogue thread mapping (tid < 204 -> (row, n)); LSTM cell state in regs
    float wl = 0.0f, c1 = 0.0f, c2 = 0.0f;
    int erow = 0, en = 0;
    if (tid < G4) {
        erow = tid / NH;
        en   = tid - erow * NH;
        wl   = Wlin[en];
    }
    const float bl = blin[0];
    float* GH = hf ? &GSb[0][0] : &GSa[0][0];

    __syncthreads();

    for (int t = 0; t < T_STEPS; ++t) {
        // prefetch x_{t+1} (hidden under S0)
        float xr = 0.0f;
        int pr = 0, pk = 0;
        if (tid < ROWS * D_IN) {
            pr = tid / D_IN;
            pk = tid - pr * D_IN;
            if (t + 1 < T_STEPS)
                xr = x[((t + 1) * M_BATCH + mbase + pr) * D_IN + pk];
        }

        // ---- S0: layer-1 gates: register weights x broadcast activations ----
        if (gate_active) {
            unsigned long long acc[2][ROWS];
            #pragma unroll
            for (int r = 0; r < ROWS; ++r) {
                acc[0][r] = pack2(b1lo, 0.0f);
                acc[1][r] = pack2(b1hi, 0.0f);
            }
            const int q0 = hf * 8;                     // ul2 indices [0,8)/[8,16)
            #pragma unroll
            for (int q = 0; q < 8; ++q) {
                #pragma unroll
                for (int r = 0; r < ROWS; ++r) {
                    ulonglong2 a = reinterpret_cast<const ulonglong2*>(&A1[r][0])[q0 + q];
                    acc[0][r] = fma2(wL1[0][2 * q],     a.x, acc[0][r]);
                    acc[0][r] = fma2(wL1[0][2 * q + 1], a.y, acc[0][r]);
                    acc[1][r] = fma2(wL1[1][2 * q],     a.x, acc[1][r]);
                    acc[1][r] = fma2(wL1[1][2 * q + 1], a.y, acc[1][r]);
                }
            }
            #pragma unroll
            for (int r = 0; r < ROWS; ++r) {
                float2 v = make_float2(sum2(acc[0][r]), sum2(acc[1][r]));
                *reinterpret_cast<float2*>(&GH[r * G4 + c0]) = v;
            }
        }
        __syncthreads();

        // ---- S1: layer-1 epilogue (thread = (row, n)) ----
        if (tid < G4) {
            float gi = GSa[erow][en]          + GSb[erow][en];
            float gf = GSa[erow][NH + en]     + GSb[erow][NH + en];
            float gg = GSa[erow][2 * NH + en] + GSb[erow][2 * NH + en];
            float go = GSa[erow][3 * NH + en] + GSb[erow][3 * NH + en];
            c1 = siga(gf) * c1 + siga(gi) * tanha(gg);
            float h = siga(go) * tanha(c1);
            A2[erow][en] = h;                 // layer-2 input (this step)
            A1[erow][D_IN + en] = h;          // layer-1 h input (next step)
        }
        if (tid < ROWS * D_IN) A1[pr][pk] = xr;   // x_{t+1}
        __syncthreads();

        // ---- S2: layer-2 gates ----
        if (gate_active) {
            unsigned long long acc[2][ROWS];
            #pragma unroll
            for (int r = 0; r < ROWS; ++r) {
                acc[0][r] = pack2(b2lo, 0.0f);
                acc[1][r] = pack2(b2hi, 0.0f);
            }
            const int q0 = hf * 13;                    // ul2 indices [0,13)/[13,26)
            #pragma unroll
            for (int q = 0; q < 13; ++q) {
                #pragma unroll
                for (int r = 0; r < ROWS; ++r) {
                    ulonglong2 a = reinterpret_cast<const ulonglong2*>(&A2[r][0])[q0 + q];
                    acc[0][r] = fma2(wL2[0][2 * q],     a.x, acc[0][r]);
                    acc[0][r] = fma2(wL2[0][2 * q + 1], a.y, acc[0][r]);
                    acc[1][r] = fma2(wL2[1][2 * q],     a.x, acc[1][r]);
                    acc[1][r] = fma2(wL2[1][2 * q + 1], a.y, acc[1][r]);
                }
            }
            #pragma unroll
            for (int r = 0; r < ROWS; ++r) {
                float2 v = make_float2(sum2(acc[0][r]), sum2(acc[1][r]));
                *reinterpret_cast<float2*>(&GH[r * G4 + c0]) = v;
            }
        }
        __syncthreads();

        // ---- S3: layer-2 epilogue ----
        if (tid < G4) {
            float gi = GSa[erow][en]          + GSb[erow][en];
            float gf = GSa[erow][NH + en]     + GSb[erow][NH + en];
            float gg = GSa[erow][2 * NH + en] + GSb[erow][2 * NH + en];
            float go = GSa[erow][3 * NH + en] + GSb[erow][3 * NH + en];
            c2 = siga(gf) * c2 + siga(gi) * tanha(gg);
            float h = siga(go) * tanha(c2);
            A2[erow][NH + en] = h;            // h2 for next step
            PO[erow][en] = h * wl;            // output partial
        }
        __syncthreads();

        // ---- S4: output reduction, warp r handles row r ----
        if (tid < 128) {
            int r = tid >> 5, lane = tid & 31;
            float v = PO[r][lane] + PO[r][32 + lane];   // [51..63] zero
            #pragma unroll
            for (int off = 16; off > 0; off >>= 1)
                v += __shfl_down_sync(0xffffffffu, v, off);
            if (lane == 0)
                out[(mbase + r) * T_STEPS + t] = v + bl;
        }
        // S4 warps rejoin at the post-S0 barrier before anyone reads GS/PO again
    }
}

extern "C" void kernel_launch(void* const* d_in, const int* in_sizes, int n_in,
                              void* d_out, int out_size) {
    const float* x    = (const float*)d_in[0];
    const float* Wih1 = (const float*)d_in[1];
    const float* Whh1 = (const float*)d_in[2];
    const float* bih1 = (const float*)d_in[3];
    const float* bhh1 = (const float*)d_in[4];
    const float* Wih2 = (const float*)d_in[5];
    const float* Whh2 = (const float*)d_in[6];
    const float* bih2 = (const float*)d_in[7];
    const float* bhh2 = (const float*)d_in[8];
    const float* Wlin = (const float*)d_in[9];
    const float* blin = (const float*)d_in[10];
    float* out = (float*)d_out;

    lstm2_persistent_kernel<<<BLOCKS, THREADS>>>(
        x, Wih1, Whh1, bih1, bhh1, Wih2, Whh2, bih2, bhh2, Wlin, blin, out);
}

// round 10
// speedup vs baseline: 2.3430x; 1.0884x over previous
#include <cuda_runtime.h>
#include <cuda_bf16.h>

// Problem constants
#define T_STEPS 4096
#define M_BATCH 512
#define D_IN    11
#define NH      51
#define G4      204          // 4*NH gate columns
#define A1S     64           // act1 row stride: x[11] | h1[51] | 2 pad
#define A2S     104          // act2 row stride: h1[51] | h2[51] | 2 pad
#define ROWS    4            // batch rows per block
#define THREADS 256          // 8 warps; hf = tid>>7; 102 col-pair threads per K-half
#define BLOCKS  128          // 128*4 = 512 rows
#define CP      102          // column-pairs (204/2)

// fast tanh (MUFU.TANH)
__device__ __forceinline__ float tanha(float x) {
    float y;
    asm("tanh.approx.f32 %0, %1;" : "=f"(y) : "f"(x));
    return y;
}
__device__ __forceinline__ float siga(float x) {
    return fmaf(0.5f, tanha(0.5f * x), 0.5f);
}

// packed 2xfp32 FMA (Blackwell f32x2 pipe)
__device__ __forceinline__ unsigned long long fma2(unsigned long long a,
                                                   unsigned long long b,
                                                   unsigned long long c) {
    unsigned long long d;
    asm("fma.rn.f32x2 %0, %1, %2, %3;" : "=l"(d) : "l"(a), "l"(b), "l"(c));
    return d;
}
__device__ __forceinline__ unsigned long long pack2(float lo, float hi) {
    unsigned long long r;
    asm("mov.b64 %0, {%1, %2};" : "=l"(r) : "f"(lo), "f"(hi));
    return r;
}
__device__ __forceinline__ float sum2(unsigned long long v) {
    float lo, hi;
    asm("mov.b64 {%0, %1}, %2;" : "=f"(lo), "=f"(hi) : "l"(v));
    return lo + hi;
}

__global__ void __launch_bounds__(THREADS, 1)
lstm2_persistent_kernel(const float* __restrict__ x,
                        const float* __restrict__ Wih1, const float* __restrict__ Whh1,
                        const float* __restrict__ bih1, const float* __restrict__ bhh1,
                        const float* __restrict__ Wih2, const float* __restrict__ Whh2,
                        const float* __restrict__ bih2, const float* __restrict__ bhh2,
                        const float* __restrict__ Wlin, const float* __restrict__ blin,
                        float* __restrict__ out)
{
    __shared__ float A1[ROWS][A1S];       // x(j)[11] | h1(j-1)[51] | pad
    __shared__ float A2[ROWS][A2S];       // h1(j-1)[51] | h2(j-2)[51] | pad
    __shared__ float GS1a[ROWS][G4];      // L1 gates, K-half-0
    __shared__ float GS1b[ROWS][G4];      // L1 gates, K-half-1
    __shared__ float GS2a[ROWS][G4];      // L2 gates, K-half-0
    __shared__ float GS2b[ROWS][G4];      // L2 gates, K-half-1
    __shared__ float PO[ROWS][64];        // output partials

    const int tid   = threadIdx.x;
    const int mbase = blockIdx.x * ROWS;
    const int hf    = tid >> 7;           // K-half, warp-uniform
    const int cp    = tid & 127;          // column-pair index
    const bool gate_active = (cp < CP);
    const int c0 = 2 * cp;                // first owned gate column

    // ---- ALL weights in per-thread registers (packed f32x2 k-pairs) ----
    unsigned long long wL1[2][16];        // 2 cols x half of padded K=64
    unsigned long long wL2[2][26];        // 2 cols x half of padded K=104
    #pragma unroll
    for (int c = 0; c < 2; ++c) {
        #pragma unroll
        for (int i = 0; i < 16; ++i) wL1[c][i] = 0ull;
        #pragma unroll
        for (int i = 0; i < 26; ++i) wL2[c][i] = 0ull;
    }
    if (gate_active) {
        #pragma unroll
        for (int c = 0; c < 2; ++c) {
            const int col = c0 + c;
            #pragma unroll
            for (int i = 0; i < 16; ++i) {
                int k0 = hf * 32 + 2 * i;
                float lo = 0.0f, hi = 0.0f;
                if (k0 < D_IN)            lo = Wih1[col * D_IN + k0];
                else if (k0 < D_IN + NH)  lo = Whh1[col * NH + (k0 - D_IN)];
                int k1 = k0 + 1;
                if (k1 < D_IN)            hi = Wih1[col * D_IN + k1];
                else if (k1 < D_IN + NH)  hi = Whh1[col * NH + (k1 - D_IN)];
                wL1[c][i] = pack2(lo, hi);
            }
            #pragma unroll
            for (int i = 0; i < 26; ++i) {
                int k0 = hf * 52 + 2 * i;
                float lo = 0.0f, hi = 0.0f;
                if (k0 < NH)            lo = Wih2[col * NH + k0];
                else if (k0 < 2 * NH)   lo = Whh2[col * NH + (k0 - NH)];
                int k1 = k0 + 1;
                if (k1 < NH)            hi = Wih2[col * NH + k1];
                else if (k1 < 2 * NH)   hi = Whh2[col * NH + (k1 - NH)];
                wL2[c][i] = pack2(lo, hi);
            }
        }
    }

    // gate biases (added only by K-half-0 threads)
    float b1lo = 0.0f, b1hi = 0.0f, b2lo = 0.0f, b2hi = 0.0f;
    if (gate_active && hf == 0) {
        b1lo = bih1[c0] + bhh1[c0];
        b1hi = bih1[c0 + 1] + bhh1[c0 + 1];
        b2lo = bih2[c0] + bhh2[c0];
        b2hi = bih2[c0 + 1] + bhh2[c0 + 1];
    }

    // ---- zero buffers, load x_0 ----
    for (int i = tid; i < ROWS * A1S; i += THREADS) (&A1[0][0])[i] = 0.0f;
    for (int i = tid; i < ROWS * A2S; i += THREADS) (&A2[0][0])[i] = 0.0f;
    for (int i = tid; i < ROWS * 64;  i += THREADS) (&PO[0][0])[i] = 0.0f;
    if (tid < ROWS * D_IN) {
        int r = tid / D_IN, k = tid - r * D_IN;
        A1[r][k] = x[(0 * M_BATCH + mbase + r) * D_IN + k];
    }

    // epilogue mapping (tid < 204 -> (row, n)); cell states in registers
    float wl = 0.0f, c1 = 0.0f, c2 = 0.0f;
    int erow = 0, en = 0;
    if (tid < G4) {
        erow = tid / NH;
        en   = tid - erow * NH;
        wl   = Wlin[en];
    }
    const float bl = blin[0];
    float* GH1 = hf ? &GS1b[0][0] : &GS1a[0][0];
    float* GH2 = hf ? &GS2b[0][0] : &GS2a[0][0];

    __syncthreads();

    // Pipelined: iteration j computes L1-gates(j) and L2-gates(j-1), then
    // epilogue h1(j), h2(j-1). Output for step j-2 reduced at top of gate phase.
    for (int j = 0; j <= T_STEPS; ++j) {
        // ---- output reduction for step j-2 (PO stable since last barrier) ----
        if (j >= 2 && tid < 128) {
            int r = tid >> 5, lane = tid & 31;
            float v = PO[r][lane] + PO[r][32 + lane];   // [51..63] zero
            #pragma unroll
            for (int off = 16; off > 0; off >>= 1)
                v += __shfl_down_sync(0xffffffffu, v, off);
            if (lane == 0)
                out[(mbase + r) * T_STEPS + (j - 2)] = v + bl;
        }

        // prefetch x_{j+1} (hidden under gate phase)
        float xr = 0.0f;
        int pr = 0, pk = 0;
        if (tid < ROWS * D_IN) {
            pr = tid / D_IN;
            pk = tid - pr * D_IN;
            if (j + 1 < T_STEPS)
                xr = x[((j + 1) * M_BATCH + mbase + pr) * D_IN + pk];
        }

        // ---- GATE PHASE: L1 gemm (step j) then L2 gemm (step j-1) ----
        if (gate_active) {
            if (j < T_STEPS) {
                unsigned long long acc[2][ROWS];
                #pragma unroll
                for (int r = 0; r < ROWS; ++r) {
                    acc[0][r] = pack2(b1lo, 0.0f);
                    acc[1][r] = pack2(b1hi, 0.0f);
                }
                const int q0 = hf * 8;
                #pragma unroll
                for (int q = 0; q < 8; ++q) {
                    #pragma unroll
                    for (int r = 0; r < ROWS; ++r) {
                        ulonglong2 a = reinterpret_cast<const ulonglong2*>(&A1[r][0])[q0 + q];
                        acc[0][r] = fma2(wL1[0][2 * q],     a.x, acc[0][r]);
                        acc[0][r] = fma2(wL1[0][2 * q + 1], a.y, acc[0][r]);
                        acc[1][r] = fma2(wL1[1][2 * q],     a.x, acc[1][r]);
                        acc[1][r] = fma2(wL1[1][2 * q + 1], a.y, acc[1][r]);
                    }
                }
                #pragma unroll
                for (int r = 0; r < ROWS; ++r) {
                    float2 v = make_float2(sum2(acc[0][r]), sum2(acc[1][r]));
                    *reinterpret_cast<float2*>(&GH1[r * G4 + c0]) = v;
                }
            }
            if (j >= 1) {
                unsigned long long acc[2][ROWS];
                #pragma unroll
                for (int r = 0; r < ROWS; ++r) {
                    acc[0][r] = pack2(b2lo, 0.0f);
                    acc[1][r] = pack2(b2hi, 0.0f);
                }
                const int q0 = hf * 13;
                #pragma unroll
                for (int q = 0; q < 13; ++q) {
                    #pragma unroll
                    for (int r = 0; r < ROWS; ++r) {
                        ulonglong2 a = reinterpret_cast<const ulonglong2*>(&A2[r][0])[q0 + q];
                        acc[0][r] = fma2(wL2[0][2 * q],     a.x, acc[0][r]);
                        acc[0][r] = fma2(wL2[0][2 * q + 1], a.y, acc[0][r]);
                        acc[1][r] = fma2(wL2[1][2 * q],     a.x, acc[1][r]);
                        acc[1][r] = fma2(wL2[1][2 * q + 1], a.y, acc[1][r]);
                    }
                }
                #pragma unroll
                for (int r = 0; r < ROWS; ++r) {
                    float2 v = make_float2(sum2(acc[0][r]), sum2(acc[1][r]));
                    *reinterpret_cast<float2*>(&GH2[r * G4 + c0]) = v;
                }
            }
        }
        __syncthreads();

        // ---- EPILOGUE PHASE: L1 cell (j) and L2 cell (j-1), independent chains ----
        if (tid < G4) {
            if (j < T_STEPS) {
                float gi = GS1a[erow][en]          + GS1b[erow][en];
                float gf = GS1a[erow][NH + en]     + GS1b[erow][NH + en];
                float gg = GS1a[erow][2 * NH + en] + GS1b[erow][2 * NH + en];
                float go = GS1a[erow][3 * NH + en] + GS1b[erow][3 * NH + en];
                c1 = siga(gf) * c1 + siga(gi) * tanha(gg);
                float h = siga(go) * tanha(c1);
                A1[erow][D_IN + en] = h;      // L1 recurrent input for j+1
                A2[erow][en]        = h;      // L2 input h1(j) for gate phase j+1
            }
            if (j >= 1) {
                float gi = GS2a[erow][en]          + GS2b[erow][en];
                float gf = GS2a[erow][NH + en]     + GS2b[erow][NH + en];
                float gg = GS2a[erow][2 * NH + en] + GS2b[erow][2 * NH + en];
                float go = GS2a[erow][3 * NH + en] + GS2b[erow][3 * NH + en];
                c2 = siga(gf) * c2 + siga(gi) * tanha(gg);
                float h = siga(go) * tanha(c2);
                A2[erow][NH + en] = h;        // h2(j-1) for gate phase j+1
                PO[erow][en] = h * wl;        // output partial, reduced next iter
            }
        }
        if (tid < ROWS * D_IN && j + 1 < T_STEPS) A1[pr][pk] = xr;  // x(j+1)
        __syncthreads();
    }

    // final output: step T-1 (PO written in iteration j=T)
    if (tid < 128) {
        int r = tid >> 5, lane = tid & 31;
        float v = PO[r][lane] + PO[r][32 + lane];
        #pragma unroll
        for (int off = 16; off > 0; off >>= 1)
            v += __shfl_down_sync(0xffffffffu, v, off);
        if (lane == 0)
            out[(mbase + r) * T_STEPS + (T_STEPS - 1)] = v + bl;
    }
}

extern "C" void kernel_launch(void* const* d_in, const int* in_sizes, int n_in,
                              void* d_out, int out_size) {
    const float* x    = (const float*)d_in[0];
    const float* Wih1 = (const float*)d_in[1];
    const float* Whh1 = (const float*)d_in[2];
    const float* bih1 = (const float*)d_in[3];
    const float* bhh1 = (const float*)d_in[4];
    const float* Wih2 = (const float*)d_in[5];
    const float* Whh2 = (const float*)d_in[6];
    const float* bih2 = (const float*)d_in[7];
    const float* bhh2 = (const float*)d_in[8];
    const float* Wlin = (const float*)d_in[9];
    const float* blin = (const float*)d_in[10];
    float* out = (float*)d_out;

    lstm2_persistent_kernel<<<BLOCKS, THREADS>>>(
        x, Wih1, Whh1, bih1, bhh1, Wih2, Whh2, bih2, bhh2, Wlin, blin, out);
}